// round 7
// baseline (speedup 1.0000x reference)
#include <cuda_runtime.h>
#include <cuda_bf16.h>

#define DIMQ 256
#define M_TILE 64
#define NTHR 256

// SMEM: xs [u=64][e=64] float4, ys [v=64][e=64] float4, wt 4 paths x [v=64][w=64] float
// = 64*64*16 * 2 + 4*4096*4 = 196608 bytes
#define SMEM_BYTES 196608

__global__ void __launch_bounds__(NTHR, 1)
fc_tp_kernel(const float* __restrict__ e1x, const float* __restrict__ e1y,
             const float* __restrict__ e2x, const float* __restrict__ e2y,
             const float* __restrict__ W1_000, const float* __restrict__ W1_110,
             const float* __restrict__ W1_011, const float* __restrict__ W1_101,
             const float* __restrict__ W2_000, const float* __restrict__ W2_110,
             const float* __restrict__ W2_011, const float* __restrict__ W2_101,
             float* __restrict__ out, int E)
{
    extern __shared__ float smem[];
    float4* xs  = reinterpret_cast<float4*>(smem);   // [u][e]
    float4* ys  = xs + 64 * 64;                      // [v][e]
    float4* wt4 = ys + 64 * 64;                      // 4 x 1024 float4: [path][v][w/4]

    const float INV_SQRT3 = 0.57735026918962576f;
    const float ALPHA0    = 0.011048543456039806f;   // 1/sqrt(2*64*64)
    const float OUT1S     = ALPHA0 * INV_SQRT3;

    const int tid = threadIdx.x;
    const int te  = tid >> 4;   // 0..15 -> edges te*4..te*4+3
    const int tw  = tid & 15;   // 0..15 -> w = tw*4..tw*4+3
    const int e0  = blockIdx.x * M_TILE;

    float acc0[4][4];
    float acc1[4][3][4];
    #pragma unroll
    for (int e = 0; e < 4; ++e) {
        #pragma unroll
        for (int w = 0; w < 4; ++w) acc0[e][w] = 0.f;
        #pragma unroll
        for (int i = 0; i < 3; ++i)
            #pragma unroll
            for (int w = 0; w < 4; ++w) acc1[e][i][w] = 0.f;
    }

    #pragma unroll 1
    for (int tp = 0; tp < 2; ++tp) {
        const float* xg = tp ? e2x : e1x;
        const float* yg = tp ? e2y : e1y;
        const float* Wa = tp ? W2_000 : W1_000;
        const float* Wb = tp ? W2_110 : W1_110;
        const float* Wc = tp ? W2_011 : W1_011;
        const float* Wd = tp ? W2_101 : W1_101;

        __syncthreads();  // guard previous iteration's ys/xs reads
        for (int idx = tid; idx < 64 * 64; idx += NTHR) {
            const int e  = idx >> 6;
            const int u  = idx & 63;
            const int ge = e0 + e;
            float4 vx = make_float4(0.f, 0.f, 0.f, 0.f);
            float4 vy = vx;
            if (ge < E) {
                const float* xr = xg + (size_t)ge * DIMQ;
                vx = make_float4(xr[u], xr[64 + 3 * u], xr[65 + 3 * u], xr[66 + 3 * u]);
                const float* yr = yg + (size_t)ge * DIMQ;
                vy = make_float4(yr[u], yr[64 + 3 * u], yr[65 + 3 * u], yr[66 + 3 * u]);
            }
            xs[u * 64 + e] = vx;
            ys[u * 64 + e] = vy;
        }
        __syncthreads();

        #pragma unroll 1
        for (int u = 0; u < 64; ++u) {
            __syncthreads();  // guard previous u's wt reads
            {
                const float4* sa = reinterpret_cast<const float4*>(Wa + (size_t)u * 4096);
                const float4* sb = reinterpret_cast<const float4*>(Wb + (size_t)u * 4096);
                const float4* sc = reinterpret_cast<const float4*>(Wc + (size_t)u * 4096);
                const float4* sd = reinterpret_cast<const float4*>(Wd + (size_t)u * 4096);
                #pragma unroll
                for (int k = 0; k < 4; ++k) {
                    const int idx = tid + k * NTHR;    // 0..1023
                    wt4[idx] = sa[idx];
                    float4 t = sb[idx];
                    t.x *= INV_SQRT3; t.y *= INV_SQRT3; t.z *= INV_SQRT3; t.w *= INV_SQRT3;
                    wt4[1024 + idx] = t;               // INV_SQRT3 folded into W110
                    wt4[2048 + idx] = sc[idx];
                    wt4[3072 + idx] = sd[idx];
                }
            }
            __syncthreads();

            float4 xv[4];
            #pragma unroll
            for (int e = 0; e < 4; ++e) xv[e] = xs[u * 64 + te * 4 + e];

            #pragma unroll 2
            for (int v = 0; v < 64; ++v) {
                const float4 b000 = wt4[v * 16 + tw];
                const float4 b110 = wt4[1024 + v * 16 + tw];
                const float4 b011 = wt4[2048 + v * 16 + tw];
                const float4 b101 = wt4[3072 + v * 16 + tw];
                const float4* yrow = ys + v * 64 + te * 4;
                #pragma unroll
                for (int e = 0; e < 4; ++e) {
                    const float4 yv = yrow[e];
                    const float s000 = xv[e].x * yv.x;
                    const float s110 = xv[e].y * yv.y + xv[e].z * yv.z + xv[e].w * yv.w;
                    acc0[e][0] += s000 * b000.x + s110 * b110.x;
                    acc0[e][1] += s000 * b000.y + s110 * b110.y;
                    acc0[e][2] += s000 * b000.z + s110 * b110.z;
                    acc0[e][3] += s000 * b000.w + s110 * b110.w;
                    const float a0 = xv[e].x * yv.y;   // x0 * y1_i
                    const float a1 = xv[e].x * yv.z;
                    const float a2 = xv[e].x * yv.w;
                    const float c0 = xv[e].y * yv.x;   // x1_i * y0
                    const float c1 = xv[e].z * yv.x;
                    const float c2 = xv[e].w * yv.x;
                    acc1[e][0][0] += a0 * b011.x + c0 * b101.x;
                    acc1[e][0][1] += a0 * b011.y + c0 * b101.y;
                    acc1[e][0][2] += a0 * b011.z + c0 * b101.z;
                    acc1[e][0][3] += a0 * b011.w + c0 * b101.w;
                    acc1[e][1][0] += a1 * b011.x + c1 * b101.x;
                    acc1[e][1][1] += a1 * b011.y + c1 * b101.y;
                    acc1[e][1][2] += a1 * b011.z + c1 * b101.z;
                    acc1[e][1][3] += a1 * b011.w + c1 * b101.w;
                    acc1[e][2][0] += a2 * b011.x + c2 * b101.x;
                    acc1[e][2][1] += a2 * b011.y + c2 * b101.y;
                    acc1[e][2][2] += a2 * b011.z + c2 * b101.z;
                    acc1[e][2][3] += a2 * b011.w + c2 * b101.w;
                }
            }
        }
    }

    #pragma unroll
    for (int e = 0; e < 4; ++e) {
        const int ge = e0 + te * 4 + e;
        if (ge < E) {
            float* o = out + (size_t)ge * DIMQ;
            #pragma unroll
            for (int w = 0; w < 4; ++w) {
                const int wg = tw * 4 + w;
                o[wg] = ALPHA0 * acc0[e][w];
                o[64 + wg * 3 + 0] = OUT1S * acc1[e][0][w];
                o[64 + wg * 3 + 1] = OUT1S * acc1[e][1][w];
                o[64 + wg * 3 + 2] = OUT1S * acc1[e][2][w];
            }
        }
    }
}

extern "C" void kernel_launch(void* const* d_in, const int* in_sizes, int n_in,
                              void* d_out, int out_size) {
    const float* e1x    = (const float*)d_in[0];
    const float* e1y    = (const float*)d_in[1];
    const float* e2x    = (const float*)d_in[2];
    const float* e2y    = (const float*)d_in[3];
    const float* W1_000 = (const float*)d_in[4];
    const float* W1_110 = (const float*)d_in[5];
    const float* W1_011 = (const float*)d_in[6];
    const float* W1_101 = (const float*)d_in[7];
    const float* W2_000 = (const float*)d_in[8];
    const float* W2_110 = (const float*)d_in[9];
    const float* W2_011 = (const float*)d_in[10];
    const float* W2_101 = (const float*)d_in[11];
    float* out = (float*)d_out;

    const int E = in_sizes[0] / DIMQ;
    const int grid = (E + M_TILE - 1) / M_TILE;

    cudaFuncSetAttribute(fc_tp_kernel,
                         cudaFuncAttributeMaxDynamicSharedMemorySize, SMEM_BYTES);
    fc_tp_kernel<<<grid, NTHR, SMEM_BYTES>>>(
        e1x, e1y, e2x, e2y,
        W1_000, W1_110, W1_011, W1_101,
        W2_000, W2_110, W2_011, W2_101,
        out, E);
}

// round 9
// speedup vs baseline: 1.0575x; 1.0575x over previous
#include <cuda_runtime.h>
#include <cuda_bf16.h>

#define DIMQ 256
#define M_TILE 64
#define NTHR 256

// SMEM: xs [u=64][e=64] float4, ys [v=64][e=64] float4, wt 4 paths x [v=64][w=64] float
// = 64*64*16 * 2 + 4*4096*4 = 196608 bytes
#define SMEM_BYTES 196608

__global__ void __launch_bounds__(NTHR, 1)
fc_tp_kernel(const float* __restrict__ e1x, const float* __restrict__ e1y,
             const float* __restrict__ e2x, const float* __restrict__ e2y,
             const float* __restrict__ W1_000, const float* __restrict__ W1_110,
             const float* __restrict__ W1_011, const float* __restrict__ W1_101,
             const float* __restrict__ W2_000, const float* __restrict__ W2_110,
             const float* __restrict__ W2_011, const float* __restrict__ W2_101,
             float* __restrict__ out, int E)
{
    extern __shared__ float smem[];
    float4* xs  = reinterpret_cast<float4*>(smem);   // [u][e]
    float4* ys  = xs + 64 * 64;                      // [v][e]
    float4* wt4 = ys + 64 * 64;                      // 4 x 1024 float4: [path][v][w/4]

    const float INV_SQRT3 = 0.57735026918962576f;
    const float ALPHA0    = 0.011048543456039806f;   // 1/sqrt(2*64*64)
    const float OUT1S     = ALPHA0 * INV_SQRT3;

    const int tid = threadIdx.x;
    const int te  = tid >> 4;   // 0..15 -> edges te*4..te*4+3
    const int tw  = tid & 15;   // 0..15 -> w = tw*4..tw*4+3
    const int e0  = blockIdx.x * M_TILE;

    float acc0[4][4];
    float acc1[4][3][4];
    #pragma unroll
    for (int e = 0; e < 4; ++e) {
        #pragma unroll
        for (int w = 0; w < 4; ++w) acc0[e][w] = 0.f;
        #pragma unroll
        for (int i = 0; i < 3; ++i)
            #pragma unroll
            for (int w = 0; w < 4; ++w) acc1[e][i][w] = 0.f;
    }

    #pragma unroll 1
    for (int tp = 0; tp < 2; ++tp) {
        const float* xg = tp ? e2x : e1x;
        const float* yg = tp ? e2y : e1y;
        const float* Wa = tp ? W2_000 : W1_000;
        const float* Wb = tp ? W2_110 : W1_110;
        const float* Wc = tp ? W2_011 : W1_011;
        const float* Wd = tp ? W2_101 : W1_101;

        __syncthreads();  // guard previous iteration's ys/xs reads
        for (int idx = tid; idx < 64 * 64; idx += NTHR) {
            const int e  = idx >> 6;
            const int u  = idx & 63;
            const int ge = e0 + e;
            float4 vx = make_float4(0.f, 0.f, 0.f, 0.f);
            float4 vy = vx;
            if (ge < E) {
                const float* xr = xg + (size_t)ge * DIMQ;
                vx = make_float4(xr[u], xr[64 + 3 * u], xr[65 + 3 * u], xr[66 + 3 * u]);
                const float* yr = yg + (size_t)ge * DIMQ;
                vy = make_float4(yr[u], yr[64 + 3 * u], yr[65 + 3 * u], yr[66 + 3 * u]);
            }
            xs[u * 64 + e] = vx;
            ys[u * 64 + e] = vy;
        }
        __syncthreads();

        #pragma unroll 1
        for (int u = 0; u < 64; ++u) {
            __syncthreads();  // guard previous u's wt reads
            {
                const float4* sa = reinterpret_cast<const float4*>(Wa + (size_t)u * 4096);
                const float4* sb = reinterpret_cast<const float4*>(Wb + (size_t)u * 4096);
                const float4* sc = reinterpret_cast<const float4*>(Wc + (size_t)u * 4096);
                const float4* sd = reinterpret_cast<const float4*>(Wd + (size_t)u * 4096);
                #pragma unroll
                for (int k = 0; k < 4; ++k) {
                    const int idx = tid + k * NTHR;    // 0..1023
                    wt4[idx] = sa[idx];
                    float4 t = sb[idx];
                    t.x *= INV_SQRT3; t.y *= INV_SQRT3; t.z *= INV_SQRT3; t.w *= INV_SQRT3;
                    wt4[1024 + idx] = t;               // INV_SQRT3 folded into W110
                    wt4[2048 + idx] = sc[idx];
                    wt4[3072 + idx] = sd[idx];
                }
            }
            __syncthreads();

            float4 xv[4];
            #pragma unroll
            for (int e = 0; e < 4; ++e) xv[e] = xs[u * 64 + te * 4 + e];

            #pragma unroll 2
            for (int v = 0; v < 64; ++v) {
                const float4 b000 = wt4[v * 16 + tw];
                const float4 b110 = wt4[1024 + v * 16 + tw];
                const float4 b011 = wt4[2048 + v * 16 + tw];
                const float4 b101 = wt4[3072 + v * 16 + tw];
                const float4* yrow = ys + v * 64 + te * 4;
                #pragma unroll
                for (int e = 0; e < 4; ++e) {
                    const float4 yv = yrow[e];
                    const float s000 = xv[e].x * yv.x;
                    const float s110 = xv[e].y * yv.y + xv[e].z * yv.z + xv[e].w * yv.w;
                    acc0[e][0] += s000 * b000.x + s110 * b110.x;
                    acc0[e][1] += s000 * b000.y + s110 * b110.y;
                    acc0[e][2] += s000 * b000.z + s110 * b110.z;
                    acc0[e][3] += s000 * b000.w + s110 * b110.w;
                    const float a0 = xv[e].x * yv.y;   // x0 * y1_i
                    const float a1 = xv[e].x * yv.z;
                    const float a2 = xv[e].x * yv.w;
                    const float c0 = xv[e].y * yv.x;   // x1_i * y0
                    const float c1 = xv[e].z * yv.x;
                    const float c2 = xv[e].w * yv.x;
                    acc1[e][0][0] += a0 * b011.x + c0 * b101.x;
                    acc1[e][0][1] += a0 * b011.y + c0 * b101.y;
                    acc1[e][0][2] += a0 * b011.z + c0 * b101.z;
                    acc1[e][0][3] += a0 * b011.w + c0 * b101.w;
                    acc1[e][1][0] += a1 * b011.x + c1 * b101.x;
                    acc1[e][1][1] += a1 * b011.y + c1 * b101.y;
                    acc1[e][1][2] += a1 * b011.z + c1 * b101.z;
                    acc1[e][1][3] += a1 * b011.w + c1 * b101.w;
                    acc1[e][2][0] += a2 * b011.x + c2 * b101.x;
                    acc1[e][2][1] += a2 * b011.y + c2 * b101.y;
                    acc1[e][2][2] += a2 * b011.z + c2 * b101.z;
                    acc1[e][2][3] += a2 * b011.w + c2 * b101.w;
                }
            }
        }
    }

    #pragma unroll
    for (int e = 0; e < 4; ++e) {
        const int ge = e0 + te * 4 + e;
        if (ge < E) {
            float* o = out + (size_t)ge * DIMQ;
            #pragma unroll
            for (int w = 0; w < 4; ++w) {
                const int wg = tw * 4 + w;
                o[wg] = ALPHA0 * acc0[e][w];
                o[64 + wg * 3 + 0] = OUT1S * acc1[e][0][w];
                o[64 + wg * 3 + 1] = OUT1S * acc1[e][1][w];
                o[64 + wg * 3 + 2] = OUT1S * acc1[e][2][w];
            }
        }
    }
}

extern "C" void kernel_launch(void* const* d_in, const int* in_sizes, int n_in,
                              void* d_out, int out_size) {
    const float* e1x    = (const float*)d_in[0];
    const float* e1y    = (const float*)d_in[1];
    const float* e2x    = (const float*)d_in[2];
    const float* e2y    = (const float*)d_in[3];
    const float* W1_000 = (const float*)d_in[4];
    const float* W1_110 = (const float*)d_in[5];
    const float* W1_011 = (const float*)d_in[6];
    const float* W1_101 = (const float*)d_in[7];
    const float* W2_000 = (const float*)d_in[8];
    const float* W2_110 = (const float*)d_in[9];
    const float* W2_011 = (const float*)d_in[10];
    const float* W2_101 = (const float*)d_in[11];
    float* out = (float*)d_out;

    const int E = in_sizes[0] / DIMQ;
    const int grid = (E + M_TILE - 1) / M_TILE;

    cudaFuncSetAttribute(fc_tp_kernel,
                         cudaFuncAttributeMaxDynamicSharedMemorySize, SMEM_BYTES);
    fc_tp_kernel<<<grid, NTHR, SMEM_BYTES>>>(
        e1x, e1y, e2x, e2y,
        W1_000, W1_110, W1_011, W1_101,
        W2_000, W2_110, W2_011, W2_101,
        out, E);
}

// round 10
// speedup vs baseline: 1.0580x; 1.0004x over previous
#include <cuda_runtime.h>
#include <cuda_bf16.h>

#define DIMQ 256
#define M_TILE 64
#define NTHR 256

// SMEM: xs [u=64][e=64] float4, ys [v=64][e=64] float4, wt 4 paths x [v=64][w=64] float
// = 64*64*16 * 2 + 4*4096*4 = 196608 bytes
#define SMEM_BYTES 196608

__global__ void __launch_bounds__(NTHR, 1)
fc_tp_kernel(const float* __restrict__ e1x, const float* __restrict__ e1y,
             const float* __restrict__ e2x, const float* __restrict__ e2y,
             const float* __restrict__ W1_000, const float* __restrict__ W1_110,
             const float* __restrict__ W1_011, const float* __restrict__ W1_101,
             const float* __restrict__ W2_000, const float* __restrict__ W2_110,
             const float* __restrict__ W2_011, const float* __restrict__ W2_101,
             float* __restrict__ out, int E)
{
    extern __shared__ float smem[];
    float4* xs  = reinterpret_cast<float4*>(smem);   // [u][e]
    float4* ys  = xs + 64 * 64;                      // [v][e]
    float4* wt4 = ys + 64 * 64;                      // 4 x 1024 float4: [path][v][w/4]

    const float INV_SQRT3 = 0.57735026918962576f;
    const float ALPHA0    = 0.011048543456039806f;   // 1/sqrt(2*64*64)
    const float OUT1S     = ALPHA0 * INV_SQRT3;

    const int tid = threadIdx.x;
    const int te  = tid >> 4;   // 0..15 -> edges te*4..te*4+3
    const int tw  = tid & 15;   // 0..15 -> w = tw*4..tw*4+3
    const int e0  = blockIdx.x * M_TILE;

    float acc0[4][4];
    float acc1[4][3][4];
    #pragma unroll
    for (int e = 0; e < 4; ++e) {
        #pragma unroll
        for (int w = 0; w < 4; ++w) acc0[e][w] = 0.f;
        #pragma unroll
        for (int i = 0; i < 3; ++i)
            #pragma unroll
            for (int w = 0; w < 4; ++w) acc1[e][i][w] = 0.f;
    }

    #pragma unroll 1
    for (int tp = 0; tp < 2; ++tp) {
        const float* xg = tp ? e2x : e1x;
        const float* yg = tp ? e2y : e1y;
        const float* Wa = tp ? W2_000 : W1_000;
        const float* Wb = tp ? W2_110 : W1_110;
        const float* Wc = tp ? W2_011 : W1_011;
        const float* Wd = tp ? W2_101 : W1_101;

        __syncthreads();  // guard previous iteration's ys/xs reads
        for (int idx = tid; idx < 64 * 64; idx += NTHR) {
            const int e  = idx >> 6;
            const int u  = idx & 63;
            const int ge = e0 + e;
            float4 vx = make_float4(0.f, 0.f, 0.f, 0.f);
            float4 vy = vx;
            if (ge < E) {
                const float* xr = xg + (size_t)ge * DIMQ;
                vx = make_float4(xr[u], xr[64 + 3 * u], xr[65 + 3 * u], xr[66 + 3 * u]);
                const float* yr = yg + (size_t)ge * DIMQ;
                vy = make_float4(yr[u], yr[64 + 3 * u], yr[65 + 3 * u], yr[66 + 3 * u]);
            }
            xs[u * 64 + e] = vx;
            ys[u * 64 + e] = vy;
        }
        __syncthreads();

        #pragma unroll 1
        for (int u = 0; u < 64; ++u) {
            __syncthreads();  // guard previous u's wt reads
            {
                const float4* sa = reinterpret_cast<const float4*>(Wa + (size_t)u * 4096);
                const float4* sb = reinterpret_cast<const float4*>(Wb + (size_t)u * 4096);
                const float4* sc = reinterpret_cast<const float4*>(Wc + (size_t)u * 4096);
                const float4* sd = reinterpret_cast<const float4*>(Wd + (size_t)u * 4096);
                #pragma unroll
                for (int k = 0; k < 4; ++k) {
                    const int idx = tid + k * NTHR;    // 0..1023
                    wt4[idx] = sa[idx];
                    float4 t = sb[idx];
                    t.x *= INV_SQRT3; t.y *= INV_SQRT3; t.z *= INV_SQRT3; t.w *= INV_SQRT3;
                    wt4[1024 + idx] = t;               // INV_SQRT3 folded into W110
                    wt4[2048 + idx] = sc[idx];
                    wt4[3072 + idx] = sd[idx];
                }
            }
            __syncthreads();

            float4 xv[4];
            #pragma unroll
            for (int e = 0; e < 4; ++e) xv[e] = xs[u * 64 + te * 4 + e];

            #pragma unroll 2
            for (int v = 0; v < 64; ++v) {
                const float4 b000 = wt4[v * 16 + tw];
                const float4 b110 = wt4[1024 + v * 16 + tw];
                const float4 b011 = wt4[2048 + v * 16 + tw];
                const float4 b101 = wt4[3072 + v * 16 + tw];
                const float4* yrow = ys + v * 64 + te * 4;
                #pragma unroll
                for (int e = 0; e < 4; ++e) {
                    const float4 yv = yrow[e];
                    const float s000 = xv[e].x * yv.x;
                    const float s110 = xv[e].y * yv.y + xv[e].z * yv.z + xv[e].w * yv.w;
                    acc0[e][0] += s000 * b000.x + s110 * b110.x;
                    acc0[e][1] += s000 * b000.y + s110 * b110.y;
                    acc0[e][2] += s000 * b000.z + s110 * b110.z;
                    acc0[e][3] += s000 * b000.w + s110 * b110.w;
                    const float a0 = xv[e].x * yv.y;   // x0 * y1_i
                    const float a1 = xv[e].x * yv.z;
                    const float a2 = xv[e].x * yv.w;
                    const float c0 = xv[e].y * yv.x;   // x1_i * y0
                    const float c1 = xv[e].z * yv.x;
                    const float c2 = xv[e].w * yv.x;
                    acc1[e][0][0] += a0 * b011.x + c0 * b101.x;
                    acc1[e][0][1] += a0 * b011.y + c0 * b101.y;
                    acc1[e][0][2] += a0 * b011.z + c0 * b101.z;
                    acc1[e][0][3] += a0 * b011.w + c0 * b101.w;
                    acc1[e][1][0] += a1 * b011.x + c1 * b101.x;
                    acc1[e][1][1] += a1 * b011.y + c1 * b101.y;
                    acc1[e][1][2] += a1 * b011.z + c1 * b101.z;
                    acc1[e][1][3] += a1 * b011.w + c1 * b101.w;
                    acc1[e][2][0] += a2 * b011.x + c2 * b101.x;
                    acc1[e][2][1] += a2 * b011.y + c2 * b101.y;
                    acc1[e][2][2] += a2 * b011.z + c2 * b101.z;
                    acc1[e][2][3] += a2 * b011.w + c2 * b101.w;
                }
            }
        }
    }

    #pragma unroll
    for (int e = 0; e < 4; ++e) {
        const int ge = e0 + te * 4 + e;
        if (ge < E) {
            float* o = out + (size_t)ge * DIMQ;
            #pragma unroll
            for (int w = 0; w < 4; ++w) {
                const int wg = tw * 4 + w;
                o[wg] = ALPHA0 * acc0[e][w];
                o[64 + wg * 3 + 0] = OUT1S * acc1[e][0][w];
                o[64 + wg * 3 + 1] = OUT1S * acc1[e][1][w];
                o[64 + wg * 3 + 2] = OUT1S * acc1[e][2][w];
            }
        }
    }
}

extern "C" void kernel_launch(void* const* d_in, const int* in_sizes, int n_in,
                              void* d_out, int out_size) {
    const float* e1x    = (const float*)d_in[0];
    const float* e1y    = (const float*)d_in[1];
    const float* e2x    = (const float*)d_in[2];
    const float* e2y    = (const float*)d_in[3];
    const float* W1_000 = (const float*)d_in[4];
    const float* W1_110 = (const float*)d_in[5];
    const float* W1_011 = (const float*)d_in[6];
    const float* W1_101 = (const float*)d_in[7];
    const float* W2_000 = (const float*)d_in[8];
    const float* W2_110 = (const float*)d_in[9];
    const float* W2_011 = (const float*)d_in[10];
    const float* W2_101 = (const float*)d_in[11];
    float* out = (float*)d_out;

    const int E = in_sizes[0] / DIMQ;
    const int grid = (E + M_TILE - 1) / M_TILE;

    cudaFuncSetAttribute(fc_tp_kernel,
                         cudaFuncAttributeMaxDynamicSharedMemorySize, SMEM_BYTES);
    fc_tp_kernel<<<grid, NTHR, SMEM_BYTES>>>(
        e1x, e1y, e2x, e2y,
        W1_000, W1_110, W1_011, W1_101,
        W2_000, W2_110, W2_011, W2_101,
        out, E);
}

// round 12
// speedup vs baseline: 4.0699x; 3.8469x over previous
#include <cuda_runtime.h>
#include <cstdint>

#define MT      96
#define NTHR    256
#define YSTRIDE 72
#define YPLANE  (96 * YSTRIDE)                 // 6912 floats per plane
#define SM_BF   (4 * YPLANE)                   // B ring base (floats) = 27648
#define SMEM_BYTES ((SM_BF + 2 * 8192) * 4)    // 110592 + 65536 = 176128

#define A0F 0.011048543456039806f              // 1/sqrt(2*64*64)
#define S1F (0.011048543456039806f * 0.57735026918962576f)

// 8 MB preprocessed weights: 256 chunks (h = 2t+seg) x 8192 floats.
// chunk layout: [0..4095] = dest-0 path tile, [4096..8191] = dest-1..3 path tile,
// each 64x64 tf32 stored in exact mma B-fragment order.
__device__ __align__(16) uint32_t g_wb[256u * 8192u];

// ---------------- helpers (generic-PTX only) ----------------
static __device__ __forceinline__ uint32_t f2tf(float f) {
    uint32_t r; asm("cvt.rna.tf32.f32 %0, %1;" : "=r"(r) : "f"(f)); return r;
}
static __device__ __forceinline__ uint32_t smaddr(const void* p) {
    uint32_t a;
    asm("{ .reg .u64 t; cvta.to.shared.u64 t, %1; cvt.u32.u64 %0, t; }" : "=r"(a) : "l"(p));
    return a;
}
static __device__ __forceinline__ void cp16(uint32_t d, const void* s) {
    asm volatile("cp.async.cg.shared.global [%0], [%1], 16;" :: "r"(d), "l"(s));
}
static __device__ __forceinline__ void cpcommit() {
    asm volatile("cp.async.commit_group;");
}
template <int N> static __device__ __forceinline__ void cpwait() {
    asm volatile("cp.async.wait_group %0;" :: "n"(N));
}
static __device__ __forceinline__ void mma8(float& c0, float& c1, float& c2, float& c3,
                                            uint32_t a0, uint32_t a1, uint32_t a2, uint32_t a3,
                                            uint32_t b0, uint32_t b1) {
    asm volatile("mma.sync.aligned.m16n8k8.row.col.f32.tf32.tf32.f32 "
                 "{%0,%1,%2,%3}, {%4,%5,%6,%7}, {%8,%9}, {%0,%1,%2,%3};"
                 : "+f"(c0), "+f"(c1), "+f"(c2), "+f"(c3)
                 : "r"(a0), "r"(a1), "r"(a2), "r"(a3), "r"(b0), "r"(b1));
}

// ---------------- prologue: weight -> fragment-layout image ----------------
// path: 0=W000(seg0,d0) 1=W110(seg1,d0) 2=W011(seg0,d123) 3=W101(seg1,d123)
__global__ void prep_w(const float* W000a, const float* W110a, const float* W011a, const float* W101a,
                       const float* W000b, const float* W110b, const float* W011b, const float* W101b)
{
    const int b = blockIdx.x;            // 0..511
    const int t = b >> 2, path = b & 3;
    const int tp = t >> 6, u = t & 63;
    const float* W;
    if (tp == 0) W = (path == 0) ? W000a : (path == 1) ? W110a : (path == 2) ? W011a : W101a;
    else         W = (path == 0) ? W000b : (path == 1) ? W110b : (path == 2) ? W011b : W101b;
    const float sc = (path == 0) ? A0F : S1F;
    const float* src = W + (size_t)u * 4096;
    uint32_t* dst = g_wb + (size_t)(2 * t + (path & 1)) * 8192 + (path >= 2 ? 4096 : 0);
    #pragma unroll
    for (int k = 0; k < 16; ++k) {
        const int idx = threadIdx.x + k * 256;      // = v*64 + w
        const int v = idx >> 6, w = idx & 63;
        const int kt = v >> 3, vi = v & 7;
        const int lane = (w & 7) * 4 + (vi >> 1);
        const int pos = ((kt * 8 + (w >> 3)) * 32 + lane) * 2 + (vi & 1);
        dst[pos] = f2tf(sc * src[idx]);
    }
}

// ---------------- main kernel ----------------
__global__ void __launch_bounds__(NTHR, 1)
fc_tp_mma(const float* __restrict__ e1x, const float* __restrict__ e1y,
          const float* __restrict__ e2x, const float* __restrict__ e2y,
          float* __restrict__ out, int E)
{
    extern __shared__ float sm[];       // planes: y0, y1x, y1y, y1z ; then B ring
    float* bring = sm + SM_BF;
    const int tid = threadIdx.x, lane = tid & 31, wid = tid >> 5;
    const int d = wid & 3, mh = wid >> 2;
    const int g = lane >> 2, c4 = lane & 3;
    const int eb = blockIdx.x * MT;

    int rows[6];
    #pragma unroll
    for (int m = 0; m < 3; ++m) { rows[2 * m] = eb + mh * 48 + m * 16 + g; rows[2 * m + 1] = rows[2 * m] + 8; }

    float C[3][8][4];
    #pragma unroll
    for (int m = 0; m < 3; ++m)
        #pragma unroll
        for (int n = 0; n < 8; ++n)
            #pragma unroll
            for (int q = 0; q < 4; ++q) C[m][n][q] = 0.f;

    const uint32_t bsm = smaddr(bring);

    // prologue: chunks 0 and 1
    {
        const char* s0 = (const char*)g_wb;
        #pragma unroll
        for (int k = 0; k < 8; ++k) cp16(bsm + (tid + k * 256) * 16, s0 + (size_t)(tid + k * 256) * 16);
        cpcommit();
        #pragma unroll
        for (int k = 0; k < 8; ++k) cp16(bsm + 32768 + (tid + k * 256) * 16, s0 + 32768 + (size_t)(tid + k * 256) * 16);
        cpcommit();
    }

    const float* xg = e1x;
    float x0v[6], x1v[6], xxv[6], xyv[6], xzv[6];

    #pragma unroll 1
    for (int h = 0; h < 256; ++h) {
        const int t = h >> 1, seg = h & 1;

        if ((h & 127) == 0) {
            const int tp = h >> 7;
            xg = tp ? e2x : e1x;
            const float* ygl = tp ? e2y : e1y;
            __syncthreads();
            // stage y0 plane (float4)
            for (int i = tid; i < 96 * 16; i += NTHR) {
                const int r = i >> 4, q = i & 15;
                const int rc = min(eb + r, E - 1);
                const float4 v = *(const float4*)(ygl + (size_t)rc * 256 + q * 4);
                float* dp = sm + r * YSTRIDE + q * 4;
                dp[0] = v.x; dp[1] = v.y; dp[2] = v.z; dp[3] = v.w;
            }
            // stage y1 planes (de-interleave stride-3)
            for (int i = tid; i < 96 * 192; i += NTHR) {
                const int r = i / 192, k = i % 192;
                const int rc = min(eb + r, E - 1);
                const float f = ygl[(size_t)rc * 256 + 64 + k];
                sm[(1 + k % 3) * YPLANE + r * YSTRIDE + k / 3] = f;
            }
            __syncthreads();
        }

        if (seg == 0) {
            const int u = t & 63;
            #pragma unroll
            for (int j = 0; j < 6; ++j) {
                const float* xr = xg + (size_t)min(rows[j], E - 1) * 256;
                x0v[j] = xr[u];
                if (d == 0) { xxv[j] = xr[64 + 3 * u]; xyv[j] = xr[65 + 3 * u]; xzv[j] = xr[66 + 3 * u]; }
                else        x1v[j] = xr[64 + 3 * u + (d - 1)];
            }
        }

        cpwait<1>();
        __syncthreads();
        const float* bs = bring + (h & 1) * 8192 + (d ? 4096 : 0);

        #pragma unroll
        for (int kt = 0; kt < 8; ++kt) {
            uint32_t bfr[8][2];
            #pragma unroll
            for (int nt = 0; nt < 8; ++nt) {
                const uint32_t* bp = (const uint32_t*)bs + ((kt * 8 + nt) * 32 + lane) * 2;
                bfr[nt][0] = bp[0]; bfr[nt][1] = bp[1];
            }
            const int vo = kt * 8 + 2 * c4;        // a0 col; a2 = vo+1 (adjacent)
            #pragma unroll
            for (int mt = 0; mt < 3; ++mt) {
                const int rA = mh * 48 + mt * 16 + g, rB = rA + 8;
                uint32_t a0, a1, a2, a3;
                if (d == 0) {
                    if (seg == 0) {                 // A_s = x0 * y0
                        const float2 pA = *(const float2*)(sm + rA * YSTRIDE + vo);
                        const float2 pB = *(const float2*)(sm + rB * YSTRIDE + vo);
                        a0 = f2tf(x0v[2 * mt] * pA.x);     a2 = f2tf(x0v[2 * mt] * pA.y);
                        a1 = f2tf(x0v[2 * mt + 1] * pB.x); a3 = f2tf(x0v[2 * mt + 1] * pB.y);
                    } else {                        // A_d = sum_i x1i * y1i
                        const float* p1 = sm + YPLANE, *p2 = sm + 2 * YPLANE, *p3 = sm + 3 * YPLANE;
                        float2 qx = *(const float2*)(p1 + rA * YSTRIDE + vo);
                        float2 qy = *(const float2*)(p2 + rA * YSTRIDE + vo);
                        float2 qz = *(const float2*)(p3 + rA * YSTRIDE + vo);
                        a0 = f2tf(xxv[2 * mt] * qx.x + xyv[2 * mt] * qy.x + xzv[2 * mt] * qz.x);
                        a2 = f2tf(xxv[2 * mt] * qx.y + xyv[2 * mt] * qy.y + xzv[2 * mt] * qz.y);
                        qx = *(const float2*)(p1 + rB * YSTRIDE + vo);
                        qy = *(const float2*)(p2 + rB * YSTRIDE + vo);
                        qz = *(const float2*)(p3 + rB * YSTRIDE + vo);
                        a1 = f2tf(xxv[2 * mt + 1] * qx.x + xyv[2 * mt + 1] * qy.x + xzv[2 * mt + 1] * qz.x);
                        a3 = f2tf(xxv[2 * mt + 1] * qx.y + xyv[2 * mt + 1] * qy.y + xzv[2 * mt + 1] * qz.y);
                    }
                } else {
                    // seg0: a_i = x0 * y1_{d-1} (plane d) ; seg1: c_i = x1_{d-1} * y0 (plane 0)
                    const float* pl = (seg == 0) ? (sm + d * YPLANE) : sm;
                    const float xf0 = (seg == 0) ? x0v[2 * mt] : x1v[2 * mt];
                    const float xf1 = (seg == 0) ? x0v[2 * mt + 1] : x1v[2 * mt + 1];
                    const float2 pA = *(const float2*)(pl + rA * YSTRIDE + vo);
                    const float2 pB = *(const float2*)(pl + rB * YSTRIDE + vo);
                    a0 = f2tf(xf0 * pA.x); a2 = f2tf(xf0 * pA.y);
                    a1 = f2tf(xf1 * pB.x); a3 = f2tf(xf1 * pB.y);
                }
                #pragma unroll
                for (int nt = 0; nt < 8; ++nt)
                    mma8(C[mt][nt][0], C[mt][nt][1], C[mt][nt][2], C[mt][nt][3],
                         a0, a1, a2, a3, bfr[nt][0], bfr[nt][1]);
            }
        }
        __syncthreads();
        if (h + 2 < 256) {
            const char* srcb = (const char*)g_wb + (size_t)(h + 2) * 32768;
            const uint32_t dstb = bsm + (h & 1) * 32768;
            #pragma unroll
            for (int k = 0; k < 8; ++k) cp16(dstb + (tid + k * 256) * 16, srcb + (size_t)(tid + k * 256) * 16);
            cpcommit();
        } else {
            cpcommit();   // empty group keeps the wait_group accounting uniform
        }
    }

    // ---------------- epilogue ----------------
    #pragma unroll
    for (int mt = 0; mt < 3; ++mt) {
        #pragma unroll
        for (int half = 0; half < 2; ++half) {
            const int e = eb + mh * 48 + mt * 16 + g + half * 8;
            if (e < E) {
                float* orow = out + (size_t)e * 256;
                #pragma unroll
                for (int nt = 0; nt < 8; ++nt) {
                    const float v0 = C[mt][nt][half * 2], v1 = C[mt][nt][half * 2 + 1];
                    const int w = nt * 8 + c4 * 2;
                    if (d == 0) {
                        *(float2*)(orow + w) = make_float2(v0, v1);
                    } else {
                        orow[64 + 3 * w + (d - 1)]       = v0;
                        orow[64 + 3 * (w + 1) + (d - 1)] = v1;
                    }
                }
            }
        }
    }
}

extern "C" void kernel_launch(void* const* d_in, const int* in_sizes, int n_in,
                              void* d_out, int out_size) {
    const float* e1x = (const float*)d_in[0];
    const float* e1y = (const float*)d_in[1];
    const float* e2x = (const float*)d_in[2];
    const float* e2y = (const float*)d_in[3];
    prep_w<<<512, 256>>>((const float*)d_in[4], (const float*)d_in[5],
                         (const float*)d_in[6], (const float*)d_in[7],
                         (const float*)d_in[8], (const float*)d_in[9],
                         (const float*)d_in[10], (const float*)d_in[11]);
    const int E = in_sizes[0] / 256;
    const int grid = (E + MT - 1) / MT;
    cudaFuncSetAttribute(fc_tp_mma, cudaFuncAttributeMaxDynamicSharedMemorySize, SMEM_BYTES);
    fc_tp_mma<<<grid, NTHR, SMEM_BYTES>>>(e1x, e1y, e2x, e2y, (float*)d_out, E);
}

// round 13
// speedup vs baseline: 5.3303x; 1.3097x over previous
#include <cuda_runtime.h>
#include <cstdint>

#define MT      96
#define NTHR    384
#define YSTRIDE 72
#define YPLANE  (96 * YSTRIDE)                 // 6912 floats per plane
#define SM_BF   (4 * YPLANE)                   // B ring base (floats) = 27648
#define SMEM_BYTES ((SM_BF + 3 * 8192) * 4)    // 110592 + 98304 = 208896

#define A0F 0.011048543456039806f              // 1/sqrt(2*64*64)
#define S1F (0.011048543456039806f * 0.57735026918962576f)

// 8 MB preprocessed weights: 256 chunks (h = 2t+seg) x 8192 floats.
// chunk layout: [0..4095] = dest-0 path tile, [4096..8191] = dest-1..3 path tile,
// each 64x64 tf32 stored in exact mma B-fragment order.
__device__ __align__(16) uint32_t g_wb[256u * 8192u];

// ---------------- helpers (generic-PTX only) ----------------
static __device__ __forceinline__ uint32_t f2tf(float f) {
    uint32_t r; asm("cvt.rna.tf32.f32 %0, %1;" : "=r"(r) : "f"(f)); return r;
}
static __device__ __forceinline__ uint32_t smaddr(const void* p) {
    uint32_t a;
    asm("{ .reg .u64 t; cvta.to.shared.u64 t, %1; cvt.u32.u64 %0, t; }" : "=r"(a) : "l"(p));
    return a;
}
static __device__ __forceinline__ void cp16(uint32_t d, const void* s) {
    asm volatile("cp.async.cg.shared.global [%0], [%1], 16;" :: "r"(d), "l"(s));
}
static __device__ __forceinline__ void cpcommit() {
    asm volatile("cp.async.commit_group;");
}
template <int N> static __device__ __forceinline__ void cpwait() {
    asm volatile("cp.async.wait_group %0;" :: "n"(N));
}
static __device__ __forceinline__ void mma8(float& c0, float& c1, float& c2, float& c3,
                                            uint32_t a0, uint32_t a1, uint32_t a2, uint32_t a3,
                                            uint32_t b0, uint32_t b1) {
    asm volatile("mma.sync.aligned.m16n8k8.row.col.f32.tf32.tf32.f32 "
                 "{%0,%1,%2,%3}, {%4,%5,%6,%7}, {%8,%9}, {%0,%1,%2,%3};"
                 : "+f"(c0), "+f"(c1), "+f"(c2), "+f"(c3)
                 : "r"(a0), "r"(a1), "r"(a2), "r"(a3), "r"(b0), "r"(b1));
}

// ---------------- prologue: weight -> fragment-layout image ----------------
// path: 0=W000(seg0,d0) 1=W110(seg1,d0) 2=W011(seg0,d123) 3=W101(seg1,d123)
__global__ void prep_w(const float* W000a, const float* W110a, const float* W011a, const float* W101a,
                       const float* W000b, const float* W110b, const float* W011b, const float* W101b)
{
    const int b = blockIdx.x;            // 0..511
    const int t = b >> 2, path = b & 3;
    const int tp = t >> 6, u = t & 63;
    const float* W;
    if (tp == 0) W = (path == 0) ? W000a : (path == 1) ? W110a : (path == 2) ? W011a : W101a;
    else         W = (path == 0) ? W000b : (path == 1) ? W110b : (path == 2) ? W011b : W101b;
    const float sc = (path == 0) ? A0F : S1F;
    const float* src = W + (size_t)u * 4096;
    uint32_t* dst = g_wb + (size_t)(2 * t + (path & 1)) * 8192 + (path >= 2 ? 4096 : 0);
    #pragma unroll
    for (int k = 0; k < 16; ++k) {
        const int idx = threadIdx.x + k * 256;      // = v*64 + w
        const int v = idx >> 6, w = idx & 63;
        const int kt = v >> 3, vi = v & 7;
        const int lane = (w & 7) * 4 + (vi >> 1);
        const int pos = ((kt * 8 + (w >> 3)) * 32 + lane) * 2 + (vi & 1);
        dst[pos] = f2tf(sc * src[idx]);
    }
}

// ---------------- main kernel ----------------
__global__ void __launch_bounds__(NTHR, 1)
fc_tp_mma(const float* __restrict__ e1x, const float* __restrict__ e1y,
          const float* __restrict__ e2x, const float* __restrict__ e2y,
          float* __restrict__ out, int E)
{
    extern __shared__ float sm[];       // planes: y0, y1x, y1y, y1z ; then B ring (3 slots)
    float* bring = sm + SM_BF;
    const int tid = threadIdx.x, lane = tid & 31, wid = tid >> 5;
    const int d = wid & 3, mh = wid >> 2;          // d in 0..3, mh in 0..2
    const int g = lane >> 2, c4 = lane & 3;
    const int eb = blockIdx.x * MT;

    int rows[4];
    #pragma unroll
    for (int m = 0; m < 2; ++m) { rows[2 * m] = eb + mh * 32 + m * 16 + g; rows[2 * m + 1] = rows[2 * m] + 8; }

    float C[2][8][4];
    #pragma unroll
    for (int m = 0; m < 2; ++m)
        #pragma unroll
        for (int n = 0; n < 8; ++n)
            #pragma unroll
            for (int q = 0; q < 4; ++q) C[m][n][q] = 0.f;

    const uint32_t bsm = smaddr(bring);

    // prologue: chunks 0 and 1 into slots 0 and 1
    {
        const char* s0 = (const char*)g_wb;
        #pragma unroll
        for (int k = 0; k < 6; ++k) {
            const int i = tid + k * NTHR;
            if (i < 2048) cp16(bsm + i * 16, s0 + (size_t)i * 16);
        }
        cpcommit();
        #pragma unroll
        for (int k = 0; k < 6; ++k) {
            const int i = tid + k * NTHR;
            if (i < 2048) cp16(bsm + 32768 + i * 16, s0 + 32768 + (size_t)i * 16);
        }
        cpcommit();
    }

    const float* xg = e1x;
    float x0v[4], x1v[4], xxv[4], xyv[4], xzv[4];

    #pragma unroll 1
    for (int h = 0; h < 256; ++h) {
        const int t = h >> 1, seg = h & 1;

        if ((h & 127) == 0) {
            const int tp = h >> 7;
            xg = tp ? e2x : e1x;
            const float* ygl = tp ? e2y : e1y;
            __syncthreads();
            // stage y0 plane (float4)
            for (int i = tid; i < 96 * 16; i += NTHR) {
                const int r = i >> 4, q = i & 15;
                const int rc = min(eb + r, E - 1);
                const float4 v = *(const float4*)(ygl + (size_t)rc * 256 + q * 4);
                float* dp = sm + r * YSTRIDE + q * 4;
                dp[0] = v.x; dp[1] = v.y; dp[2] = v.z; dp[3] = v.w;
            }
            // stage y1 planes (de-interleave stride-3)
            for (int i = tid; i < 96 * 192; i += NTHR) {
                const int r = i / 192, k = i % 192;
                const int rc = min(eb + r, E - 1);
                const float f = ygl[(size_t)rc * 256 + 64 + k];
                sm[(1 + k % 3) * YPLANE + r * YSTRIDE + k / 3] = f;
            }
            __syncthreads();
        }

        if (seg == 0) {
            const int u = t & 63;
            #pragma unroll
            for (int j = 0; j < 4; ++j) {
                const float* xr = xg + (size_t)min(rows[j], E - 1) * 256;
                x0v[j] = xr[u];
                if (d == 0) { xxv[j] = xr[64 + 3 * u]; xyv[j] = xr[65 + 3 * u]; xzv[j] = xr[66 + 3 * u]; }
                else        x1v[j] = xr[64 + 3 * u + (d - 1)];
            }
        }

        cpwait<1>();
        __syncthreads();
        const float* bs = bring + (h % 3) * 8192 + (d ? 4096 : 0);

        #pragma unroll
        for (int kt = 0; kt < 8; ++kt) {
            uint32_t bfr[8][2];
            #pragma unroll
            for (int nt = 0; nt < 8; ++nt) {
                const uint32_t* bp = (const uint32_t*)bs + ((kt * 8 + nt) * 32 + lane) * 2;
                bfr[nt][0] = bp[0]; bfr[nt][1] = bp[1];
            }
            const int vo = kt * 8 + 2 * c4;        // a0 col; a2 = vo+1 (adjacent)
            #pragma unroll
            for (int mt = 0; mt < 2; ++mt) {
                const int rA = mh * 32 + mt * 16 + g, rB = rA + 8;
                uint32_t a0, a1, a2, a3;
                if (d == 0) {
                    if (seg == 0) {                 // A_s = x0 * y0
                        const float2 pA = *(const float2*)(sm + rA * YSTRIDE + vo);
                        const float2 pB = *(const float2*)(sm + rB * YSTRIDE + vo);
                        a0 = f2tf(x0v[2 * mt] * pA.x);     a2 = f2tf(x0v[2 * mt] * pA.y);
                        a1 = f2tf(x0v[2 * mt + 1] * pB.x); a3 = f2tf(x0v[2 * mt + 1] * pB.y);
                    } else {                        // A_d = sum_i x1i * y1i
                        const float* p1 = sm + YPLANE, *p2 = sm + 2 * YPLANE, *p3 = sm + 3 * YPLANE;
                        float2 qx = *(const float2*)(p1 + rA * YSTRIDE + vo);
                        float2 qy = *(const float2*)(p2 + rA * YSTRIDE + vo);
                        float2 qz = *(const float2*)(p3 + rA * YSTRIDE + vo);
                        a0 = f2tf(xxv[2 * mt] * qx.x + xyv[2 * mt] * qy.x + xzv[2 * mt] * qz.x);
                        a2 = f2tf(xxv[2 * mt] * qx.y + xyv[2 * mt] * qy.y + xzv[2 * mt] * qz.y);
                        qx = *(const float2*)(p1 + rB * YSTRIDE + vo);
                        qy = *(const float2*)(p2 + rB * YSTRIDE + vo);
                        qz = *(const float2*)(p3 + rB * YSTRIDE + vo);
                        a1 = f2tf(xxv[2 * mt + 1] * qx.x + xyv[2 * mt + 1] * qy.x + xzv[2 * mt + 1] * qz.x);
                        a3 = f2tf(xxv[2 * mt + 1] * qx.y + xyv[2 * mt + 1] * qy.y + xzv[2 * mt + 1] * qz.y);
                    }
                } else {
                    // seg0: a_i = x0 * y1_{d-1} (plane d) ; seg1: c_i = x1_{d-1} * y0 (plane 0)
                    const float* pl = (seg == 0) ? (sm + d * YPLANE) : sm;
                    const float xf0 = (seg == 0) ? x0v[2 * mt] : x1v[2 * mt];
                    const float xf1 = (seg == 0) ? x0v[2 * mt + 1] : x1v[2 * mt + 1];
                    const float2 pA = *(const float2*)(pl + rA * YSTRIDE + vo);
                    const float2 pB = *(const float2*)(pl + rB * YSTRIDE + vo);
                    a0 = f2tf(xf0 * pA.x); a2 = f2tf(xf0 * pA.y);
                    a1 = f2tf(xf1 * pB.x); a3 = f2tf(xf1 * pB.y);
                }
                #pragma unroll
                for (int nt = 0; nt < 8; ++nt)
                    mma8(C[mt][nt][0], C[mt][nt][1], C[mt][nt][2], C[mt][nt][3],
                         a0, a1, a2, a3, bfr[nt][0], bfr[nt][1]);
            }
        }

        // prefetch chunk h+2 into ring slot (h+2)%3 — never the slot being read,
        // and per-iteration barriers bound warp skew to <1 iteration, so no
        // pre-write barrier is needed.
        if (h + 2 < 256) {
            const char* srcb = (const char*)g_wb + (size_t)(h + 2) * 32768;
            const uint32_t dstb = bsm + ((h + 2) % 3) * 32768;
            #pragma unroll
            for (int k = 0; k < 6; ++k) {
                const int i = tid + k * NTHR;
                if (i < 2048) cp16(dstb + i * 16, srcb + (size_t)i * 16);
            }
            cpcommit();
        } else {
            cpcommit();   // empty group keeps the wait_group accounting uniform
        }
    }

    // ---------------- epilogue ----------------
    #pragma unroll
    for (int mt = 0; mt < 2; ++mt) {
        #pragma unroll
        for (int half = 0; half < 2; ++half) {
            const int e = eb + mh * 32 + mt * 16 + g + half * 8;
            if (e < E) {
                float* orow = out + (size_t)e * 256;
                #pragma unroll
                for (int nt = 0; nt < 8; ++nt) {
                    const float v0 = C[mt][nt][half * 2], v1 = C[mt][nt][half * 2 + 1];
                    const int w = nt * 8 + c4 * 2;
                    if (d == 0) {
                        *(float2*)(orow + w) = make_float2(v0, v1);
                    } else {
                        orow[64 + 3 * w + (d - 1)]       = v0;
                        orow[64 + 3 * (w + 1) + (d - 1)] = v1;
                    }
                }
            }
        }
    }
}

extern "C" void kernel_launch(void* const* d_in, const int* in_sizes, int n_in,
                              void* d_out, int out_size) {
    const float* e1x = (const float*)d_in[0];
    const float* e1y = (const float*)d_in[1];
    const float* e2x = (const float*)d_in[2];
    const float* e2y = (const float*)d_in[3];
    prep_w<<<512, 256>>>((const float*)d_in[4], (const float*)d_in[5],
                         (const float*)d_in[6], (const float*)d_in[7],
                         (const float*)d_in[8], (const float*)d_in[9],
                         (const float*)d_in[10], (const float*)d_in[11]);
    const int E = in_sizes[0] / 256;
    const int grid = (E + MT - 1) / MT;
    cudaFuncSetAttribute(fc_tp_mma, cudaFuncAttributeMaxDynamicSharedMemorySize, SMEM_BYTES);
    fc_tp_mma<<<grid, NTHR, SMEM_BYTES>>>(e1x, e1y, e2x, e2y, (float*)d_out, E);
}

// round 14
// speedup vs baseline: 5.6481x; 1.0596x over previous
#include <cuda_runtime.h>
#include <cstdint>

#define MT      96
#define NTHR    384
#define YPLANE  (96 * 64)                      // 6144 floats per plane (swizzled, no pad)
#define SM_BF   (4 * YPLANE)                   // B ring base (floats) = 24576
#define SMEM_BYTES ((SM_BF + 4 * 8192) * 4)    // 98304 + 131072 = 229376

#define A0F 0.011048543456039806f              // 1/sqrt(2*64*64)
#define S1F (0.011048543456039806f * 0.57735026918962576f)

// 8 MB preprocessed weights: 256 chunks (h = 2t+seg) x 8192 floats.
// chunk layout: [0..4095] = dest-0 path tile, [4096..8191] = dest-1..3 path tile,
// each 64x64 tf32 stored in exact mma B-fragment order.
__device__ __align__(16) uint32_t g_wb[256u * 8192u];

// ---------------- helpers (generic-PTX only) ----------------
static __device__ __forceinline__ uint32_t f2tf(float f) {
    uint32_t r; asm("cvt.rna.tf32.f32 %0, %1;" : "=r"(r) : "f"(f)); return r;
}
static __device__ __forceinline__ uint32_t smaddr(const void* p) {
    uint32_t a;
    asm("{ .reg .u64 t; cvta.to.shared.u64 t, %1; cvt.u32.u64 %0, t; }" : "=r"(a) : "l"(p));
    return a;
}
static __device__ __forceinline__ void cp16(uint32_t d, const void* s) {
    asm volatile("cp.async.cg.shared.global [%0], [%1], 16;" :: "r"(d), "l"(s));
}
static __device__ __forceinline__ void cpcommit() {
    asm volatile("cp.async.commit_group;");
}
template <int N> static __device__ __forceinline__ void cpwait() {
    asm volatile("cp.async.wait_group %0;" :: "n"(N));
}
static __device__ __forceinline__ void mma8(float& c0, float& c1, float& c2, float& c3,
                                            uint32_t a0, uint32_t a1, uint32_t a2, uint32_t a3,
                                            uint32_t b0, uint32_t b1) {
    asm volatile("mma.sync.aligned.m16n8k8.row.col.f32.tf32.tf32.f32 "
                 "{%0,%1,%2,%3}, {%4,%5,%6,%7}, {%8,%9}, {%0,%1,%2,%3};"
                 : "+f"(c0), "+f"(c1), "+f"(c2), "+f"(c3)
                 : "r"(a0), "r"(a1), "r"(a2), "r"(a3), "r"(b0), "r"(b1));
}
// conflict-free y-plane column swizzle: XOR the k-tile bits with row&7
static __device__ __forceinline__ int swz(int row, int col) {
    return (col & 7) | ((((col >> 3) ^ row) & 7) << 3);
}

// ---------------- prologue: weight -> fragment-layout image ----------------
// path: 0=W000(seg0,d0) 1=W110(seg1,d0) 2=W011(seg0,d123) 3=W101(seg1,d123)
__global__ void prep_w(const float* W000a, const float* W110a, const float* W011a, const float* W101a,
                       const float* W000b, const float* W110b, const float* W011b, const float* W101b)
{
    const int b = blockIdx.x;            // 0..511
    const int t = b >> 2, path = b & 3;
    const int tp = t >> 6, u = t & 63;
    const float* W;
    if (tp == 0) W = (path == 0) ? W000a : (path == 1) ? W110a : (path == 2) ? W011a : W101a;
    else         W = (path == 0) ? W000b : (path == 1) ? W110b : (path == 2) ? W011b : W101b;
    const float sc = (path == 0) ? A0F : S1F;
    const float* src = W + (size_t)u * 4096;
    uint32_t* dst = g_wb + (size_t)(2 * t + (path & 1)) * 8192 + (path >= 2 ? 4096 : 0);
    #pragma unroll
    for (int k = 0; k < 16; ++k) {
        const int idx = threadIdx.x + k * 256;      // = v*64 + w
        const int v = idx >> 6, w = idx & 63;
        const int kt = v >> 3, vi = v & 7;
        const int lane = (w & 7) * 4 + (vi >> 1);
        const int pos = ((kt * 8 + (w >> 3)) * 32 + lane) * 2 + (vi & 1);
        dst[pos] = f2tf(sc * src[idx]);
    }
}

// ---------------- main kernel ----------------
__global__ void __launch_bounds__(NTHR, 1)
fc_tp_mma(const float* __restrict__ e1x, const float* __restrict__ e1y,
          const float* __restrict__ e2x, const float* __restrict__ e2y,
          float* __restrict__ out, int E)
{
    extern __shared__ float sm[];       // planes: y0, y1x, y1y, y1z (swizzled) ; B ring (4 slots)
    float* bring = sm + SM_BF;
    const int tid = threadIdx.x, lane = tid & 31, wid = tid >> 5;
    const int d = wid & 3, mh = wid >> 2;          // d in 0..3, mh in 0..2
    const int g = lane >> 2, c4 = lane & 3;
    const int eb = blockIdx.x * MT;

    int rows[4];
    #pragma unroll
    for (int m = 0; m < 2; ++m) { rows[2 * m] = eb + mh * 32 + m * 16 + g; rows[2 * m + 1] = rows[2 * m] + 8; }

    float C[2][8][4];
    #pragma unroll
    for (int m = 0; m < 2; ++m)
        #pragma unroll
        for (int n = 0; n < 8; ++n)
            #pragma unroll
            for (int q = 0; q < 4; ++q) C[m][n][q] = 0.f;

    const uint32_t bsm = smaddr(bring);

    // prime: chunks 0,1 (t=0) into ring slots 0,1
    {
        const char* s0 = (const char*)g_wb;
        #pragma unroll
        for (int k = 0; k < 11; ++k) {
            const int i = tid + k * NTHR;
            if (i < 4096) cp16(bsm + i * 16, s0 + (size_t)i * 16);
        }
        cpcommit();
    }

    const float* xg = e1x;
    float x0v[4], x1v[4], xxv[4], xyv[4], xzv[4];

    #pragma unroll 1
    for (int t = 0; t < 128; ++t) {
        if ((t & 63) == 0) {
            const int tp = t >> 6;
            xg = tp ? e2x : e1x;
            const float* ygl = tp ? e2y : e1y;
            __syncthreads();
            // stage y0 plane (float4, swizzled cols)
            for (int i = tid; i < 96 * 16; i += NTHR) {
                const int r = i >> 4, q = i & 15;
                const int rc = min(eb + r, E - 1);
                const float4 v = *(const float4*)(ygl + (size_t)rc * 256 + q * 4);
                float* dp = sm + r * 64 + swz(r, q * 4);
                dp[0] = v.x; dp[1] = v.y; dp[2] = v.z; dp[3] = v.w;
            }
            // stage y1 planes (de-interleave stride-3, swizzled cols)
            for (int i = tid; i < 96 * 192; i += NTHR) {
                const int r = i / 192, k = i % 192;
                const int rc = min(eb + r, E - 1);
                const float f = ygl[(size_t)rc * 256 + 64 + k];
                sm[(1 + k % 3) * YPLANE + r * 64 + swz(r, k / 3)] = f;
            }
            __syncthreads();
        }

        // per-t x scalars
        {
            const int u = t & 63;
            #pragma unroll
            for (int j = 0; j < 4; ++j) {
                const float* xr = xg + (size_t)min(rows[j], E - 1) * 256;
                x0v[j] = xr[u];
                if (d == 0) { xxv[j] = xr[64 + 3 * u]; xyv[j] = xr[65 + 3 * u]; xzv[j] = xr[66 + 3 * u]; }
                else        x1v[j] = xr[64 + 3 * u + (d - 1)];
            }
        }

        cpwait<0>();
        __syncthreads();

        // distance-1 prefetch: 64KB for t+1 into the ring pair NOT being read
        if (t < 127) {
            const char* srcb = (const char*)g_wb + (size_t)(t + 1) * 65536;
            const uint32_t dstb = bsm + (uint32_t)((t + 1) & 1) * 65536;
            #pragma unroll
            for (int k = 0; k < 11; ++k) {
                const int i = tid + k * NTHR;
                if (i < 4096) cp16(dstb + i * 16, srcb + (size_t)i * 16);
            }
            cpcommit();
        }

        #pragma unroll
        for (int seg = 0; seg < 2; ++seg) {
            const float* bs = bring + ((t & 1) * 2 + seg) * 8192 + (d ? 4096 : 0);

            #pragma unroll
            for (int kt = 0; kt < 8; ++kt) {
                uint32_t bfr[8][2];
                #pragma unroll
                for (int nt = 0; nt < 8; ++nt) {
                    const uint32_t* bp = (const uint32_t*)bs + ((kt * 8 + nt) * 32 + lane) * 2;
                    bfr[nt][0] = bp[0]; bfr[nt][1] = bp[1];
                }
                const int vo = kt * 8 + 2 * c4;        // a0 col; a2 = vo+1 (adjacent, same k-tile)
                #pragma unroll
                for (int mt = 0; mt < 2; ++mt) {
                    const int rA = mh * 32 + mt * 16 + g, rB = rA + 8;
                    const int oA = rA * 64 + swz(rA, vo);
                    const int oB = rB * 64 + swz(rB, vo);
                    uint32_t a0, a1, a2, a3;
                    if (d == 0) {
                        if (seg == 0) {                 // A_s = x0 * y0
                            const float2 pA = *(const float2*)(sm + oA);
                            const float2 pB = *(const float2*)(sm + oB);
                            a0 = f2tf(x0v[2 * mt] * pA.x);     a2 = f2tf(x0v[2 * mt] * pA.y);
                            a1 = f2tf(x0v[2 * mt + 1] * pB.x); a3 = f2tf(x0v[2 * mt + 1] * pB.y);
                        } else {                        // A_d = sum_i x1i * y1i
                            const float* p1 = sm + YPLANE, *p2 = sm + 2 * YPLANE, *p3 = sm + 3 * YPLANE;
                            float2 qx = *(const float2*)(p1 + oA);
                            float2 qy = *(const float2*)(p2 + oA);
                            float2 qz = *(const float2*)(p3 + oA);
                            a0 = f2tf(xxv[2 * mt] * qx.x + xyv[2 * mt] * qy.x + xzv[2 * mt] * qz.x);
                            a2 = f2tf(xxv[2 * mt] * qx.y + xyv[2 * mt] * qy.y + xzv[2 * mt] * qz.y);
                            qx = *(const float2*)(p1 + oB);
                            qy = *(const float2*)(p2 + oB);
                            qz = *(const float2*)(p3 + oB);
                            a1 = f2tf(xxv[2 * mt + 1] * qx.x + xyv[2 * mt + 1] * qy.x + xzv[2 * mt + 1] * qz.x);
                            a3 = f2tf(xxv[2 * mt + 1] * qx.y + xyv[2 * mt + 1] * qy.y + xzv[2 * mt + 1] * qz.y);
                        }
                    } else {
                        // seg0: a_i = x0 * y1_{d-1} (plane d) ; seg1: c_i = x1_{d-1} * y0 (plane 0)
                        const float* pl = (seg == 0) ? (sm + d * YPLANE) : sm;
                        const float xf0 = (seg == 0) ? x0v[2 * mt] : x1v[2 * mt];
                        const float xf1 = (seg == 0) ? x0v[2 * mt + 1] : x1v[2 * mt + 1];
                        const float2 pA = *(const float2*)(pl + oA);
                        const float2 pB = *(const float2*)(pl + oB);
                        a0 = f2tf(xf0 * pA.x); a2 = f2tf(xf0 * pA.y);
                        a1 = f2tf(xf1 * pB.x); a3 = f2tf(xf1 * pB.y);
                    }
                    #pragma unroll
                    for (int nt = 0; nt < 8; ++nt)
                        mma8(C[mt][nt][0], C[mt][nt][1], C[mt][nt][2], C[mt][nt][3],
                             a0, a1, a2, a3, bfr[nt][0], bfr[nt][1]);
                }
            }
        }
    }

    // ---------------- epilogue ----------------
    #pragma unroll
    for (int mt = 0; mt < 2; ++mt) {
        #pragma unroll
        for (int half = 0; half < 2; ++half) {
            const int e = eb + mh * 32 + mt * 16 + g + half * 8;
            if (e < E) {
                float* orow = out + (size_t)e * 256;
                #pragma unroll
                for (int nt = 0; nt < 8; ++nt) {
                    const float v0 = C[mt][nt][half * 2], v1 = C[mt][nt][half * 2 + 1];
                    const int w = nt * 8 + c4 * 2;
                    if (d == 0) {
                        *(float2*)(orow + w) = make_float2(v0, v1);
                    } else {
                        orow[64 + 3 * w + (d - 1)]       = v0;
                        orow[64 + 3 * (w + 1) + (d - 1)] = v1;
                    }
                }
            }
        }
    }
}

extern "C" void kernel_launch(void* const* d_in, const int* in_sizes, int n_in,
                              void* d_out, int out_size) {
    const float* e1x = (const float*)d_in[0];
    const float* e1y = (const float*)d_in[1];
    const float* e2x = (const float*)d_in[2];
    const float* e2y = (const float*)d_in[3];
    prep_w<<<512, 256>>>((const float*)d_in[4], (const float*)d_in[5],
                         (const float*)d_in[6], (const float*)d_in[7],
                         (const float*)d_in[8], (const float*)d_in[9],
                         (const float*)d_in[10], (const float*)d_in[11]);
    const int E = in_sizes[0] / 256;
    const int grid = (E + MT - 1) / MT;
    cudaFuncSetAttribute(fc_tp_mma, cudaFuncAttributeMaxDynamicSharedMemorySize, SMEM_BYTES);
    fc_tp_mma<<<grid, NTHR, SMEM_BYTES>>>(e1x, e1y, e2x, e2y, (float*)d_out, E);
}

// round 16
// speedup vs baseline: 6.2109x; 1.0996x over previous
#include <cuda_runtime.h>
#include <cstdint>

#define MT      96
#define NTHR    384
#define YPLANE  (96 * 64)                      // 6144 floats per plane (swizzled, no pad)
#define SM_BF   (4 * YPLANE)                   // B ring base (floats) = 24576
#define SMEM_BYTES ((SM_BF + 4 * 8192) * 4)    // 98304 + 131072 = 229376

#define A0F 0.011048543456039806f              // 1/sqrt(2*64*64)
#define S1F (0.011048543456039806f * 0.57735026918962576f)

// 8 MB preprocessed weights: 256 chunks (h = 2t+seg) x 8192 floats.
// chunk layout: [0..4095] = dest-0 path tile, [4096..8191] = dest-1..3 path tile,
// each 64x64 tf32 stored in PAIRED mma B-fragment order (LDS.128-loadable).
__device__ __align__(16) uint32_t g_wb[256u * 8192u];

// ---------------- helpers (generic-PTX only) ----------------
static __device__ __forceinline__ uint32_t f2tf(float f) {
    uint32_t r; asm("cvt.rna.tf32.f32 %0, %1;" : "=r"(r) : "f"(f)); return r;
}
static __device__ __forceinline__ uint32_t smaddr(const void* p) {
    uint32_t a;
    asm("{ .reg .u64 t; cvta.to.shared.u64 t, %1; cvt.u32.u64 %0, t; }" : "=r"(a) : "l"(p));
    return a;
}
static __device__ __forceinline__ void cp16(uint32_t d, const void* s) {
    asm volatile("cp.async.cg.shared.global [%0], [%1], 16;" :: "r"(d), "l"(s));
}
static __device__ __forceinline__ void cpcommit() {
    asm volatile("cp.async.commit_group;");
}
template <int N> static __device__ __forceinline__ void cpwait() {
    asm volatile("cp.async.wait_group %0;" :: "n"(N));
}
static __device__ __forceinline__ void mma8(float& c0, float& c1, float& c2, float& c3,
                                            uint32_t a0, uint32_t a1, uint32_t a2, uint32_t a3,
                                            uint32_t b0, uint32_t b1) {
    asm volatile("mma.sync.aligned.m16n8k8.row.col.f32.tf32.tf32.f32 "
                 "{%0,%1,%2,%3}, {%4,%5,%6,%7}, {%8,%9}, {%0,%1,%2,%3};"
                 : "+f"(c0), "+f"(c1), "+f"(c2), "+f"(c3)
                 : "r"(a0), "r"(a1), "r"(a2), "r"(a3), "r"(b0), "r"(b1));
}
// conflict-free y-plane column swizzle: XOR the k-tile bits with row&7
static __device__ __forceinline__ int swz(int row, int col) {
    return (col & 7) | ((((col >> 3) ^ row) & 7) << 3);
}

// ---------------- prologue: weight -> paired fragment-layout image ----------------
// path: 0=W000(seg0,d0) 1=W110(seg1,d0) 2=W011(seg0,d123) 3=W101(seg1,d123)
__global__ void prep_w(const float* W000a, const float* W110a, const float* W011a, const float* W101a,
                       const float* W000b, const float* W110b, const float* W011b, const float* W101b)
{
    const int b = blockIdx.x;            // 0..511
    const int t = b >> 2, path = b & 3;
    const int tp = t >> 6, u = t & 63;
    const float* W;
    if (tp == 0) W = (path == 0) ? W000a : (path == 1) ? W110a : (path == 2) ? W011a : W101a;
    else         W = (path == 0) ? W000b : (path == 1) ? W110b : (path == 2) ? W011b : W101b;
    const float sc = (path == 0) ? A0F : S1F;
    const float* src = W + (size_t)u * 4096;
    uint32_t* dst = g_wb + (size_t)(2 * t + (path & 1)) * 8192 + (path >= 2 ? 4096 : 0);
    #pragma unroll
    for (int k = 0; k < 16; ++k) {
        const int idx = threadIdx.x + k * 256;      // = v*64 + w
        const int v = idx >> 6, w = idx & 63;
        const int kt = v >> 3, vi = v & 7;
        const int lane = (w & 7) * 4 + (vi >> 1);
        const int nt = w >> 3;
        // paired layout: lane holds 4 consecutive words = fragments (kt,2p) and (kt,2p+1)
        const int pos = ((kt * 4 + (nt >> 1)) * 32 + lane) * 4 + (nt & 1) * 2 + (vi & 1);
        dst[pos] = f2tf(sc * src[idx]);
    }
}

// ---------------- main kernel ----------------
__global__ void __launch_bounds__(NTHR, 1)
fc_tp_mma(const float* __restrict__ e1x, const float* __restrict__ e1y,
          const float* __restrict__ e2x, const float* __restrict__ e2y,
          float* __restrict__ out, int E)
{
    extern __shared__ float sm[];       // planes: y0, y1x, y1y, y1z (tf32, swizzled) ; B ring (4 slots)
    float* bring = sm + SM_BF;
    const int tid = threadIdx.x, lane = tid & 31, wid = tid >> 5;
    const int d = wid & 3, mh = wid >> 2;          // d in 0..3, mh in 0..2
    const int g = lane >> 2, c4 = lane & 3;
    const int eb = blockIdx.x * MT;

    int rows[4];
    #pragma unroll
    for (int m = 0; m < 2; ++m) { rows[2 * m] = eb + mh * 32 + m * 16 + g; rows[2 * m + 1] = rows[2 * m] + 8; }

    float C[2][8][4];
    #pragma unroll
    for (int m = 0; m < 2; ++m)
        #pragma unroll
        for (int n = 0; n < 8; ++n)
            #pragma unroll
            for (int q = 0; q < 4; ++q) C[m][n][q] = 0.f;

    const uint32_t bsm = smaddr(bring);

    // prime: chunks 0,1 (t=0) into ring slots 0,1
    {
        const char* s0 = (const char*)g_wb;
        #pragma unroll
        for (int k = 0; k < 11; ++k) {
            const int i = tid + k * NTHR;
            if (i < 4096) cp16(bsm + i * 16, s0 + (size_t)i * 16);
        }
        cpcommit();
    }

    const float* xg = e1x;
    float x0v[4], x1v[4], xxv[4], xyv[4], xzv[4];

    #pragma unroll 1
    for (int t = 0; t < 128; ++t) {
        if ((t & 63) == 0) {
            const int tp = t >> 6;
            xg = tp ? e2x : e1x;
            const float* ygl = tp ? e2y : e1y;
            __syncthreads();
            // stage y0 plane (float4, swizzled cols, tf32-rounded)
            for (int i = tid; i < 96 * 16; i += NTHR) {
                const int r = i >> 4, q = i & 15;
                const int rc = min(eb + r, E - 1);
                const float4 v = *(const float4*)(ygl + (size_t)rc * 256 + q * 4);
                float* dp = sm + r * 64 + swz(r, q * 4);
                dp[0] = __uint_as_float(f2tf(v.x)); dp[1] = __uint_as_float(f2tf(v.y));
                dp[2] = __uint_as_float(f2tf(v.z)); dp[3] = __uint_as_float(f2tf(v.w));
            }
            // stage y1 planes (de-interleave stride-3, swizzled cols, tf32-rounded)
            for (int i = tid; i < 96 * 192; i += NTHR) {
                const int r = i / 192, k = i % 192;
                const int rc = min(eb + r, E - 1);
                const float f = ygl[(size_t)rc * 256 + 64 + k];
                sm[(1 + k % 3) * YPLANE + r * 64 + swz(r, k / 3)] = __uint_as_float(f2tf(f));
            }
            __syncthreads();
        }

        // per-t x scalars (raw f32; HW truncation after product handles tf32)
        {
            const int u = t & 63;
            #pragma unroll
            for (int j = 0; j < 4; ++j) {
                const float* xr = xg + (size_t)min(rows[j], E - 1) * 256;
                x0v[j] = xr[u];
                if (d == 0) { xxv[j] = xr[64 + 3 * u]; xyv[j] = xr[65 + 3 * u]; xzv[j] = xr[66 + 3 * u]; }
                else        x1v[j] = xr[64 + 3 * u + (d - 1)];
            }
        }

        cpwait<0>();
        __syncthreads();

        // distance-1 prefetch: 64KB for t+1 into the ring pair NOT being read
        if (t < 127) {
            const char* srcb = (const char*)g_wb + (size_t)(t + 1) * 65536;
            const uint32_t dstb = bsm + (uint32_t)((t + 1) & 1) * 65536;
            #pragma unroll
            for (int k = 0; k < 11; ++k) {
                const int i = tid + k * NTHR;
                if (i < 4096) cp16(dstb + i * 16, srcb + (size_t)i * 16);
            }
            cpcommit();
        }

        #pragma unroll
        for (int seg = 0; seg < 2; ++seg) {
            const float* bs = bring + ((t & 1) * 2 + seg) * 8192 + (d ? 4096 : 0);

            #pragma unroll
            for (int kt = 0; kt < 8; ++kt) {
                uint32_t bfr[8][2];
                #pragma unroll
                for (int np = 0; np < 4; ++np) {
                    const uint4 q = *(const uint4*)((const uint32_t*)bs + ((kt * 4 + np) * 32 + lane) * 4);
                    bfr[2 * np][0] = q.x; bfr[2 * np][1] = q.y;
                    bfr[2 * np + 1][0] = q.z; bfr[2 * np + 1][1] = q.w;
                }
                const int vo = kt * 8 + 2 * c4;        // a0 col; a2 = vo+1 (adjacent, same k-tile)
                #pragma unroll
                for (int mt = 0; mt < 2; ++mt) {
                    const int rA = mh * 32 + mt * 16 + g, rB = rA + 8;
                    const int oA = rA * 64 + swz(rA, vo);
                    const int oB = rB * 64 + swz(rB, vo);
                    uint32_t a0, a1, a2, a3;
                    if (d == 0) {
                        if (seg == 0) {                 // A_s = x0 * y0
                            const float2 pA = *(const float2*)(sm + oA);
                            const float2 pB = *(const float2*)(sm + oB);
                            a0 = __float_as_uint(x0v[2 * mt] * pA.x);
                            a2 = __float_as_uint(x0v[2 * mt] * pA.y);
                            a1 = __float_as_uint(x0v[2 * mt + 1] * pB.x);
                            a3 = __float_as_uint(x0v[2 * mt + 1] * pB.y);
                        } else {                        // A_d = sum_i x1i * y1i
                            const float* p1 = sm + YPLANE, *p2 = sm + 2 * YPLANE, *p3 = sm + 3 * YPLANE;
                            float2 qx = *(const float2*)(p1 + oA);
                            float2 qy = *(const float2*)(p2 + oA);
                            float2 qz = *(const float2*)(p3 + oA);
                            a0 = __float_as_uint(xxv[2 * mt] * qx.x + xyv[2 * mt] * qy.x + xzv[2 * mt] * qz.x);
                            a2 = __float_as_uint(xxv[2 * mt] * qx.y + xyv[2 * mt] * qy.y + xzv[2 * mt] * qz.y);
                            qx = *(const float2*)(p1 + oB);
                            qy = *(const float2*)(p2 + oB);
                            qz = *(const float2*)(p3 + oB);
                            a1 = __float_as_uint(xxv[2 * mt + 1] * qx.x + xyv[2 * mt + 1] * qy.x + xzv[2 * mt + 1] * qz.x);
                            a3 = __float_as_uint(xxv[2 * mt + 1] * qx.y + xyv[2 * mt + 1] * qy.y + xzv[2 * mt + 1] * qz.y);
                        }
                    } else {
                        // seg0: a_i = x0 * y1_{d-1} (plane d) ; seg1: c_i = x1_{d-1} * y0 (plane 0)
                        const float* pl = (seg == 0) ? (sm + d * YPLANE) : sm;
                        const float xf0 = (seg == 0) ? x0v[2 * mt] : x1v[2 * mt];
                        const float xf1 = (seg == 0) ? x0v[2 * mt + 1] : x1v[2 * mt + 1];
                        const float2 pA = *(const float2*)(pl + oA);
                        const float2 pB = *(const float2*)(pl + oB);
                        a0 = __float_as_uint(xf0 * pA.x); a2 = __float_as_uint(xf0 * pA.y);
                        a1 = __float_as_uint(xf1 * pB.x); a3 = __float_as_uint(xf1 * pB.y);
                    }
                    #pragma unroll
                    for (int nt = 0; nt < 8; ++nt)
                        mma8(C[mt][nt][0], C[mt][nt][1], C[mt][nt][2], C[mt][nt][3],
                             a0, a1, a2, a3, bfr[nt][0], bfr[nt][1]);
                }
            }
        }
    }

    // ---------------- epilogue ----------------
    #pragma unroll
    for (int mt = 0; mt < 2; ++mt) {
        #pragma unroll
        for (int half = 0; half < 2; ++half) {
            const int e = eb + mh * 32 + mt * 16 + g + half * 8;
            if (e < E) {
                float* orow = out + (size_t)e * 256;
                #pragma unroll
                for (int nt = 0; nt < 8; ++nt) {
                    const float v0 = C[mt][nt][half * 2], v1 = C[mt][nt][half * 2 + 1];
                    const int w = nt * 8 + c4 * 2;
                    if (d == 0) {
                        *(float2*)(orow + w) = make_float2(v0, v1);
                    } else {
                        orow[64 + 3 * w + (d - 1)]       = v0;
                        orow[64 + 3 * (w + 1) + (d - 1)] = v1;
                    }
                }
            }
        }
    }
}

extern "C" void kernel_launch(void* const* d_in, const int* in_sizes, int n_in,
                              void* d_out, int out_size) {
    const float* e1x = (const float*)d_in[0];
    const float* e1y = (const float*)d_in[1];
    const float* e2x = (const float*)d_in[2];
    const float* e2y = (const float*)d_in[3];
    prep_w<<<512, 256>>>((const float*)d_in[4], (const float*)d_in[5],
                         (const float*)d_in[6], (const float*)d_in[7],
                         (const float*)d_in[8], (const float*)d_in[9],
                         (const float*)d_in[10], (const float*)d_in[11]);
    const int E = in_sizes[0] / 256;
    const int grid = (E + MT - 1) / MT;
    cudaFuncSetAttribute(fc_tp_mma, cudaFuncAttributeMaxDynamicSharedMemorySize, SMEM_BYTES);
    fc_tp_mma<<<grid, NTHR, SMEM_BYTES>>>(e1x, e1y, e2x, e2y, (float*)d_out, E);
}